// round 5
// baseline (speedup 1.0000x reference)
#include <cuda_runtime.h>
#include <math.h>

#define BB 2
#define NN 2048
#define CC 256
#define HH 8
#define DHH 32
#define TABW (2*NN-1)
#define SCALE 0.17677669529663687f  // 1/sqrt(32)

typedef unsigned long long u64;

// ---- scratch ----
__device__ float g_qT[BB*HH*DHH*NN];   // [bh][d][n], pre-scaled
__device__ float g_kT[BB*HH*DHH*NN];   // [bh][d][n]
__device__ float g_v [BB*HH*NN*DHH];   // [bh][n][d]
__device__ float g_ctx[BB*NN*CC];
__device__ float g_tab[HH*TABW];
__device__ float g_pm[HH*NN];
__device__ float g_pinv[HH*NN];

// ---- f32x2 helpers ----
__device__ __forceinline__ void fma2(u64 &acc, u64 a, u64 b) {
    asm("fma.rn.f32x2 %0, %1, %2, %0;" : "+l"(acc) : "l"(a), "l"(b));
}
__device__ __forceinline__ u64 dup2(float x) {
    u64 r; asm("mov.b64 %0, {%1, %1};" : "=l"(r) : "f"(x)); return r;
}
__device__ __forceinline__ float2 unpack2(u64 v) {
    float2 r; asm("mov.b64 {%0, %1}, %2;" : "=f"(r.x), "=f"(r.y) : "l"(v)); return r;
}

// ============================================================
// 1) positional logit table
// ============================================================
__global__ void pos_tab_kernel(const float* __restrict__ Wpos,
                               const float* __restrict__ bpos) {
    int idx = blockIdx.x * blockDim.x + threadIdx.x;
    if (idx >= HH * TABW) return;
    int h = idx / TABW, dd = idx % TABW;
    float d = (float)(dd - (NN - 1));
    g_tab[idx] = Wpos[h] * d + Wpos[HH + h] * fabsf(d) + bpos[h];
}

// ============================================================
// 2) pos softmax row stats (analytic max)
// ============================================================
__global__ void pos_row_kernel() {
    int w = blockIdx.x * 8 + (threadIdx.x >> 5);
    int lane = threadIdx.x & 31;
    int h = w / NN, i = w % NN;
    const float* tab = g_tab + h * TABW;
    float m = fmaxf(fmaxf(tab[i], tab[i + NN - 1]), tab[NN - 1]);
    float s = 0.f;
    for (int j = lane; j < NN; j += 32)
        s += __expf(tab[i + NN - 1 - j] - m);
    #pragma unroll
    for (int o = 16; o; o >>= 1) s += __shfl_xor_sync(0xffffffffu, s, o);
    if (lane == 0) { g_pm[h*NN + i] = m; g_pinv[h*NN + i] = 1.f / s; }
}

// ============================================================
// 3) QKV GEMM -> g_qT (scaled), g_kT, g_v
// ============================================================
__global__ void qkv_gemm_kernel(const float* __restrict__ x,
                                const float* __restrict__ Wqk,
                                const float* __restrict__ Wv) {
    __shared__ float As[16][64];
    __shared__ float Bs[16][64];
    int tid = threadIdx.x;
    int ty = tid >> 4, tx = tid & 15;
    int m0 = blockIdx.x * 64, n0 = blockIdx.y * 64;
    float acc[4][4] = {};
    int arow = tid >> 2, acol = (tid & 3) * 4;
    int brow = tid >> 4, bcol = (tid & 15) * 4;

    for (int k0 = 0; k0 < 256; k0 += 16) {
        float4 av = *(const float4*)&x[(m0 + arow) * 256 + k0 + acol];
        As[acol + 0][arow] = av.x; As[acol + 1][arow] = av.y;
        As[acol + 2][arow] = av.z; As[acol + 3][arow] = av.w;
        int gc = n0 + bcol;
        float4 bv;
        if (gc < 512) bv = *(const float4*)&Wqk[(k0 + brow) * 512 + gc];
        else          bv = *(const float4*)&Wv[(k0 + brow) * 256 + gc - 512];
        *(float4*)&Bs[brow][bcol] = bv;
        __syncthreads();
        #pragma unroll
        for (int kk = 0; kk < 16; kk++) {
            float4 a = *(float4*)&As[kk][4 * ty];
            float4 b = *(float4*)&Bs[kk][4 * tx];
            float aa[4] = {a.x, a.y, a.z, a.w};
            float bb[4] = {b.x, b.y, b.z, b.w};
            #pragma unroll
            for (int i = 0; i < 4; i++)
                #pragma unroll
                for (int j = 0; j < 4; j++)
                    acc[i][j] += aa[i] * bb[j];
        }
        __syncthreads();
    }
    #pragma unroll
    for (int i = 0; i < 4; i++) {
        int m = m0 + 4 * ty + i;
        int b = m >> 11, n = m & (NN - 1);
        #pragma unroll
        for (int j = 0; j < 4; j++) {
            int c = n0 + 4 * tx + j;
            float v = acc[i][j];
            if (c < 256) {
                int h = c >> 5, d = c & 31;
                g_qT[((b * HH + h) * DHH + d) * NN + n] = v * SCALE;
            } else if (c < 512) {
                int cc = c - 256; int h = cc >> 5, d = cc & 31;
                g_kT[((b * HH + h) * DHH + d) * NN + n] = v;
            } else {
                int cc = c - 512; int h = cc >> 5, d = cc & 31;
                g_v[((b * HH + h) * NN + n) * DHH + d] = v;
            }
        }
    }
}

// ============================================================
// helper: load a [32][128] transposed tile into smem pad-132
// ============================================================
__device__ __forceinline__ void load_tile_T132(float (*dst)[132],
                                               const float* __restrict__ src,
                                               int n0, int tid) {
    #pragma unroll
    for (int r = 0; r < 4; r++) {
        int idx = tid + r * 256;
        int c  = idx & 15;
        int d  = (idx >> 4) & 31;
        int h2 = idx >> 9;
        int col = 4 * (c + 16 * h2);
        float4 v = *(const float4*)&src[d * NN + n0 + col];
        *(float4*)&dst[d][col] = v;
    }
}

// ============================================================
// 4) FUSED single-pass attention.
//    Per block: 128 q-rows of one (b,h). For each 32-key tile:
//      QK (f32x2) -> exp -> accumulate l, PV_patch, PV_pos.
//    Final: out = (1-g)/l * num_patch + g*pinv * num_pos.
// ============================================================
__global__ void __launch_bounds__(256) attn_fused_kernel(const float* __restrict__ gating) {
    __shared__ float qs[32][132];    // [d][q]
    __shared__ float ksd[32][68];    // [d][2*k] duplicated pairs (row 272B, 16-aligned)
    __shared__ float vs[32][36];     // [k][d]
    __shared__ float pT[32][132];    // [k][q] weights (reused patch/pos)
    __shared__ float ts[160];
    __shared__ float pmsh[128];

    int tid = threadIdx.x;
    int ty = tid >> 4, tx = tid & 15;
    int qt = blockIdx.x, h = blockIdx.y, b = blockIdx.z;
    int bh = b * HH + h;
    int q0 = qt * 128;
    const float* qg = g_qT + bh * DHH * NN;
    const float* kg = g_kT + bh * DHH * NN;
    const float* vg = g_v  + bh * NN * DHH;

    load_tile_T132(qs, qg, q0, tid);
    if (tid < 128) pmsh[tid] = g_pm[h * NN + q0 + tid];
    __syncthreads();

    // per-thread row constants
    float pmr[8];
    #pragma unroll
    for (int r = 0; r < 8; r++) pmr[r] = pmsh[8 * ty + r];

    int dx = tid & 7, ks2 = (tid >> 3) & 1;   // dx = tx&7, ks2 = tx>>3
    u64 oaccP[4][4] = {};   // patch numerator
    u64 oaccQ[4][4] = {};   // pos numerator
    float l[8] = {};

    for (int kt = 0; kt < 64; kt++) {
        int k0 = kt * 32;
        __syncthreads();
        {   // loads: ksd (duplicated), vs, ts
            int d = tid >> 3, c = tid & 7;
            float4 kv = *(const float4*)&kg[d * NN + k0 + 4 * c];
            *(float4*)&ksd[d][8 * c]     = make_float4(kv.x, kv.x, kv.y, kv.y);
            *(float4*)&ksd[d][8 * c + 4] = make_float4(kv.z, kv.z, kv.w, kv.w);
            *(float4*)&vs[d][4 * c] = *(const float4*)&vg[(k0 + d) * DHH + 4 * c];
            if (tid < 159) ts[tid] = g_tab[h * TABW + q0 - k0 + 2016 + tid];
        }
        __syncthreads();

        // ---- QK: 8q x 2k per thread ----
        u64 sacc[4][2] = {};
        #pragma unroll
        for (int d = 0; d < 32; d++) {
            ulonglong2 a0 = *(const ulonglong2*)&qs[d][8 * ty];
            ulonglong2 a1 = *(const ulonglong2*)&qs[d][8 * ty + 4];
            u64 ap[4] = {a0.x, a0.y, a1.x, a1.y};
            u64 bd0 = *(const u64*)&ksd[d][2 * tx];
            u64 bd1 = *(const u64*)&ksd[d][2 * tx + 32];
            #pragma unroll
            for (int p = 0; p < 4; p++) {
                fma2(sacc[p][0], ap[p], bd0);
                fma2(sacc[p][1], ap[p], bd1);
            }
        }
        // ---- patch weights -> pT, accumulate l ----
        #pragma unroll
        for (int p = 0; p < 4; p++) {
            int i0 = 8 * ty + 2 * p;
            #pragma unroll
            for (int j = 0; j < 2; j++) {
                int kc = tx + 16 * j;
                float2 s = unpack2(sacc[p][j]);
                float e0 = __expf(s.x), e1 = __expf(s.y);
                pT[kc][i0] = e0; pT[kc][i0 + 1] = e1;
                l[2*p] += e0; l[2*p+1] += e1;
            }
        }
        __syncthreads();
        // ---- PV patch ----
        #pragma unroll
        for (int kk = 0; kk < 16; kk++) {
            int k = 2 * kk + ks2;
            ulonglong2 a0 = *(const ulonglong2*)&pT[k][8 * ty];
            ulonglong2 a1 = *(const ulonglong2*)&pT[k][8 * ty + 4];
            u64 ap[4] = {a0.x, a0.y, a1.x, a1.y};
            float4 bv = *(const float4*)&vs[k][4 * dx];
            u64 bd[4] = {dup2(bv.x), dup2(bv.y), dup2(bv.z), dup2(bv.w)};
            #pragma unroll
            for (int p = 0; p < 4; p++)
                #pragma unroll
                for (int j = 0; j < 4; j++)
                    fma2(oaccP[p][j], ap[p], bd[j]);
        }
        __syncthreads();
        // ---- pos weights -> pT ----
        #pragma unroll
        for (int p = 0; p < 4; p++) {
            int i0 = 8 * ty + 2 * p;
            #pragma unroll
            for (int j = 0; j < 2; j++) {
                int kc = tx + 16 * j;
                float w0 = __expf(ts[i0     - kc + 31] - pmr[2*p]);
                float w1 = __expf(ts[i0 + 1 - kc + 31] - pmr[2*p+1]);
                pT[kc][i0] = w0; pT[kc][i0 + 1] = w1;
            }
        }
        __syncthreads();
        // ---- PV pos ----
        #pragma unroll
        for (int kk = 0; kk < 16; kk++) {
            int k = 2 * kk + ks2;
            ulonglong2 a0 = *(const ulonglong2*)&pT[k][8 * ty];
            ulonglong2 a1 = *(const ulonglong2*)&pT[k][8 * ty + 4];
            u64 ap[4] = {a0.x, a0.y, a1.x, a1.y};
            float4 bv = *(const float4*)&vs[k][4 * dx];
            u64 bd[4] = {dup2(bv.x), dup2(bv.y), dup2(bv.z), dup2(bv.w)};
            #pragma unroll
            for (int p = 0; p < 4; p++)
                #pragma unroll
                for (int j = 0; j < 4; j++)
                    fma2(oaccQ[p][j], ap[p], bd[j]);
        }
    }

    // ---- reduce l across the 16 tx lanes of each row group ----
    #pragma unroll
    for (int o = 8; o; o >>= 1)
        #pragma unroll
        for (int r = 0; r < 8; r++)
            l[r] += __shfl_xor_sync(0xffffffffu, l[r], o);

    float gv = 1.f / (1.f + __expf(-gating[h]));
    float s1[8], s2[8];
    #pragma unroll
    for (int r = 0; r < 8; r++) {
        int row = q0 + 8 * ty + r;
        s1[r] = (1.f - gv) / l[r];
        s2[r] = gv * g_pinv[h * NN + row];
    }
    // ---- combine, split-k reduce, store ----
    #pragma unroll
    for (int p = 0; p < 4; p++)
        #pragma unroll
        for (int j = 0; j < 4; j++) {
            float2 vp = unpack2(oaccP[p][j]);
            float2 vq = unpack2(oaccQ[p][j]);
            float o0 = s1[2*p]   * vp.x + s2[2*p]   * vq.x;
            float o1 = s1[2*p+1] * vp.y + s2[2*p+1] * vq.y;
            o0 += __shfl_xor_sync(0xffffffffu, o0, 8);
            o1 += __shfl_xor_sync(0xffffffffu, o1, 8);
            if (tx < 8) {
                int row = q0 + 8 * ty + 2 * p;
                int col = h * 32 + 4 * tx + j;
                g_ctx[(b * NN + row) * CC + col]     = o0;
                g_ctx[(b * NN + row + 1) * CC + col] = o1;
            }
        }
}

// ============================================================
// 5) Output projection
// ============================================================
__global__ void proj_gemm_kernel(const float* __restrict__ Wp,
                                 const float* __restrict__ bp,
                                 float* __restrict__ out) {
    __shared__ float As[16][64];
    __shared__ float Bs[16][64];
    int tid = threadIdx.x;
    int ty = tid >> 4, tx = tid & 15;
    int m0 = blockIdx.x * 64, n0 = blockIdx.y * 64;
    float acc[4][4] = {};
    int arow = tid >> 2, acol = (tid & 3) * 4;
    int brow = tid >> 4, bcol = (tid & 15) * 4;

    for (int k0 = 0; k0 < 256; k0 += 16) {
        float4 av = *(const float4*)&g_ctx[(m0 + arow) * 256 + k0 + acol];
        As[acol + 0][arow] = av.x; As[acol + 1][arow] = av.y;
        As[acol + 2][arow] = av.z; As[acol + 3][arow] = av.w;
        float4 bv = *(const float4*)&Wp[(k0 + brow) * 256 + n0 + bcol];
        *(float4*)&Bs[brow][bcol] = bv;
        __syncthreads();
        #pragma unroll
        for (int kk = 0; kk < 16; kk++) {
            float4 a = *(float4*)&As[kk][4 * ty];
            float4 b = *(float4*)&Bs[kk][4 * tx];
            float aa[4] = {a.x, a.y, a.z, a.w};
            float bb[4] = {b.x, b.y, b.z, b.w};
            #pragma unroll
            for (int i = 0; i < 4; i++)
                #pragma unroll
                for (int j = 0; j < 4; j++)
                    acc[i][j] += aa[i] * bb[j];
        }
        __syncthreads();
    }
    #pragma unroll
    for (int i = 0; i < 4; i++) {
        int m = m0 + 4 * ty + i;
        #pragma unroll
        for (int j = 0; j < 4; j++) {
            int c = n0 + 4 * tx + j;
            out[m * 256 + c] = acc[i][j] + bp[c];
        }
    }
}

// ============================================================
extern "C" void kernel_launch(void* const* d_in, const int* in_sizes, int n_in,
                              void* d_out, int out_size) {
    const float* x     = (const float*)d_in[0];
    const float* Wqk   = (const float*)d_in[1];
    const float* Wv    = (const float*)d_in[2];
    const float* Wproj = (const float*)d_in[3];
    const float* bproj = (const float*)d_in[4];
    const float* Wpos  = (const float*)d_in[5];
    const float* bpos  = (const float*)d_in[6];
    const float* gate  = (const float*)d_in[7];
    float* out = (float*)d_out;

    pos_tab_kernel<<<(HH * TABW + 255) / 256, 256>>>(Wpos, bpos);
    pos_row_kernel<<<HH * NN / 8, 256>>>();
    qkv_gemm_kernel<<<dim3(BB * NN / 64, 12), 256>>>(x, Wqk, Wv);
    attn_fused_kernel<<<dim3(NN / 128, HH, BB), 256>>>(gate);
    proj_gemm_kernel<<<dim3(BB * NN / 64, 4), 256>>>(Wproj, bproj, out);
}

// round 6
// speedup vs baseline: 1.2436x; 1.2436x over previous
#include <cuda_runtime.h>
#include <math.h>

#define BB 2
#define NN 2048
#define CC 256
#define HH 8
#define DHH 32
#define TABW (2*NN-1)
#define SCALE 0.17677669529663687f  // 1/sqrt(32)

typedef unsigned long long u64;

// ---- scratch ----
__device__ float g_qT[BB*HH*DHH*NN];   // [bh][d][n], pre-scaled
__device__ float g_kT[BB*HH*DHH*NN];   // [bh][d][n]
__device__ float g_v [BB*HH*NN*DHH];   // [bh][n][d]
__device__ float g_ctx[BB*NN*CC];
__device__ float g_tab[HH*TABW];
__device__ float g_pm[HH*NN];
__device__ float g_pinv[HH*NN];
__device__ float g_scanF[BB*HH*NN*DHH];  // fwd scan, then pos numerator (in-place)
__device__ float g_scanG[BB*HH*NN*DHH];  // bwd scan

// ---- f32x2 helpers ----
__device__ __forceinline__ void fma2(u64 &acc, u64 a, u64 b) {
    asm("fma.rn.f32x2 %0, %1, %2, %0;" : "+l"(acc) : "l"(a), "l"(b));
}
__device__ __forceinline__ u64 dup2(float x) {
    u64 r; asm("mov.b64 %0, {%1, %1};" : "=l"(r) : "f"(x)); return r;
}
__device__ __forceinline__ float2 unpack2(u64 v) {
    float2 r; asm("mov.b64 {%0, %1}, %2;" : "=f"(r.x), "=f"(r.y) : "l"(v)); return r;
}

// ============================================================
// 1) positional logit table
// ============================================================
__global__ void pos_tab_kernel(const float* __restrict__ Wpos,
                               const float* __restrict__ bpos) {
    int idx = blockIdx.x * blockDim.x + threadIdx.x;
    if (idx >= HH * TABW) return;
    int h = idx / TABW, dd = idx % TABW;
    float d = (float)(dd - (NN - 1));
    g_tab[idx] = Wpos[h] * d + Wpos[HH + h] * fabsf(d) + bpos[h];
}

// ============================================================
// 2) pos softmax row stats (analytic max)
// ============================================================
__global__ void pos_row_kernel() {
    int w = blockIdx.x * 8 + (threadIdx.x >> 5);
    int lane = threadIdx.x & 31;
    int h = w / NN, i = w % NN;
    const float* tab = g_tab + h * TABW;
    float m = fmaxf(fmaxf(tab[i], tab[i + NN - 1]), tab[NN - 1]);
    float s = 0.f;
    for (int j = lane; j < NN; j += 32)
        s += __expf(tab[i + NN - 1 - j] - m);
    #pragma unroll
    for (int o = 16; o; o >>= 1) s += __shfl_xor_sync(0xffffffffu, s, o);
    if (lane == 0) { g_pm[h*NN + i] = m; g_pinv[h*NN + i] = 1.f / s; }
}

// ============================================================
// 3) QKV GEMM -> g_qT (scaled), g_kT, g_v
// ============================================================
__global__ void qkv_gemm_kernel(const float* __restrict__ x,
                                const float* __restrict__ Wqk,
                                const float* __restrict__ Wv) {
    __shared__ float As[16][64];
    __shared__ float Bs[16][64];
    int tid = threadIdx.x;
    int ty = tid >> 4, tx = tid & 15;
    int m0 = blockIdx.x * 64, n0 = blockIdx.y * 64;
    float acc[4][4] = {};
    int arow = tid >> 2, acol = (tid & 3) * 4;
    int brow = tid >> 4, bcol = (tid & 15) * 4;

    for (int k0 = 0; k0 < 256; k0 += 16) {
        float4 av = *(const float4*)&x[(m0 + arow) * 256 + k0 + acol];
        As[acol + 0][arow] = av.x; As[acol + 1][arow] = av.y;
        As[acol + 2][arow] = av.z; As[acol + 3][arow] = av.w;
        int gc = n0 + bcol;
        float4 bv;
        if (gc < 512) bv = *(const float4*)&Wqk[(k0 + brow) * 512 + gc];
        else          bv = *(const float4*)&Wv[(k0 + brow) * 256 + gc - 512];
        *(float4*)&Bs[brow][bcol] = bv;
        __syncthreads();
        #pragma unroll
        for (int kk = 0; kk < 16; kk++) {
            float4 a = *(float4*)&As[kk][4 * ty];
            float4 b = *(float4*)&Bs[kk][4 * tx];
            float aa[4] = {a.x, a.y, a.z, a.w};
            float bb[4] = {b.x, b.y, b.z, b.w};
            #pragma unroll
            for (int i = 0; i < 4; i++)
                #pragma unroll
                for (int j = 0; j < 4; j++)
                    acc[i][j] += aa[i] * bb[j];
        }
        __syncthreads();
    }
    #pragma unroll
    for (int i = 0; i < 4; i++) {
        int m = m0 + 4 * ty + i;
        int b = m >> 11, n = m & (NN - 1);
        #pragma unroll
        for (int j = 0; j < 4; j++) {
            int c = n0 + 4 * tx + j;
            float v = acc[i][j];
            if (c < 256) {
                int h = c >> 5, d = c & 31;
                g_qT[((b * HH + h) * DHH + d) * NN + n] = v * SCALE;
            } else if (c < 512) {
                int cc = c - 256; int h = cc >> 5, d = cc & 31;
                g_kT[((b * HH + h) * DHH + d) * NN + n] = v;
            } else {
                int cc = c - 512; int h = cc >> 5, d = cc & 31;
                g_v[((b * HH + h) * NN + n) * DHH + d] = v;
            }
        }
    }
}

// ============================================================
// 4) POS path via exponential scans: O(N*Dh) per head.
//    one block per (b,h): warp0 fwd scan, warp1 bwd scan, then apply.
//    Writes pos numerator (Σ_j exp(tab(i-j)-pm_i) v_j) into g_scanF.
// ============================================================
__global__ void __launch_bounds__(256) pos_scan_kernel(const float* __restrict__ Wpos,
                                                       const float* __restrict__ bpos) {
    int bh = blockIdx.x;
    int h = bh & (HH - 1);
    int tid = threadIdx.x;
    int wid = tid >> 5, lane = tid & 31;
    float apos = Wpos[h] + Wpos[HH + h];   // slope for d>0 (j<i side)
    float aneg = Wpos[HH + h] - Wpos[h];   // slope for d<0 (j>i side)
    const float* vp = g_v + bh * NN * DHH + lane;
    float* fo = g_scanF + bh * NN * DHH + lane;
    float* go = g_scanG + bh * NN * DHH + lane;

    if (wid == 0) {
        // forward: F_i over j<=i
        float F = 0.f;
        if (apos <= 0.f) {
            float rho = __expf(apos);
            for (int ib = 0; ib < NN; ib += 8) {
                float vb[8];
                #pragma unroll
                for (int u = 0; u < 8; u++) vb[u] = vp[(ib + u) * DHH];
                #pragma unroll
                for (int u = 0; u < 8; u++) { F = rho * F + vb[u]; fo[(ib + u) * DHH] = F; }
            }
        } else {
            for (int ib = 0; ib < NN; ib += 8) {
                float vb[8], w[8];
                #pragma unroll
                for (int u = 0; u < 8; u++) vb[u] = vp[(ib + u) * DHH];
                #pragma unroll
                for (int u = 0; u < 8; u++) w[u] = __expf(-apos * (float)(ib + u));
                #pragma unroll
                for (int u = 0; u < 8; u++) { F += vb[u] * w[u]; fo[(ib + u) * DHH] = F; }
            }
        }
    } else if (wid == 1) {
        // backward: G_i over j>i
        float G = 0.f;
        go[(NN - 1) * DHH] = 0.f;
        if (aneg <= 0.f) {
            float rho = __expf(aneg);
            int i = NN - 2;
            for (; i >= 7; i -= 8) {
                float vb[8];
                #pragma unroll
                for (int u = 0; u < 8; u++) vb[u] = vp[(i + 1 - u) * DHH];
                #pragma unroll
                for (int u = 0; u < 8; u++) { G = rho * (G + vb[u]); go[(i - u) * DHH] = G; }
            }
            for (; i >= 0; i--) { G = rho * (G + vp[(i + 1) * DHH]); go[i * DHH] = G; }
        } else {
            int i = NN - 2;
            for (; i >= 7; i -= 8) {
                float vb[8], w[8];
                #pragma unroll
                for (int u = 0; u < 8; u++) vb[u] = vp[(i + 1 - u) * DHH];
                #pragma unroll
                for (int u = 0; u < 8; u++) w[u] = __expf(-aneg * (float)(NN - 2 - (i - u)));
                #pragma unroll
                for (int u = 0; u < 8; u++) { G += vb[u] * w[u]; go[(i - u) * DHH] = G; }
            }
            for (; i >= 0; i--) {
                G += vp[(i + 1) * DHH] * __expf(-aneg * (float)(NN - 2 - i));
                go[i * DHH] = G;
            }
        }
    }
    __syncthreads();

    // apply: pnum_i = e^{b+phi_i-pm_i} * F~_i + e^{b+psi_i-pm_i} * G~_i   (in-place into g_scanF)
    float bph = bpos[h];
    float pp = fmaxf(apos, 0.f), pn = fmaxf(aneg, 0.f);
    int d4 = tid & 7;           // float4 index within row
    int ir = tid >> 3;          // 0..31
    const float* pmrow = g_pm + h * NN;
    float* fbase = g_scanF + bh * NN * DHH;
    float* gbase = g_scanG + bh * NN * DHH;
    for (int i = ir; i < NN; i += 32) {
        float pm = pmrow[i];
        float c1 = __expf(bph + pp * (float)i - pm);
        float c2 = __expf(bph + pn * (float)(NN - 1 - i) - pm);
        float4 f = *(float4*)&fbase[i * DHH + 4 * d4];
        float4 g = *(float4*)&gbase[i * DHH + 4 * d4];
        float4 r;
        r.x = c1 * f.x + c2 * g.x;
        r.y = c1 * f.y + c2 * g.y;
        r.z = c1 * f.z + c2 * g.z;
        r.w = c1 * f.w + c2 * g.w;
        *(float4*)&fbase[i * DHH + 4 * d4] = r;
    }
}

// ============================================================
// helper: load a [32][128] transposed tile into smem pad-132
// ============================================================
__device__ __forceinline__ void load_tile_T132(float (*dst)[132],
                                               const float* __restrict__ src,
                                               int n0, int tid) {
    #pragma unroll
    for (int r = 0; r < 4; r++) {
        int idx = tid + r * 256;
        int c  = idx & 15;
        int d  = (idx >> 4) & 31;
        int h2 = idx >> 9;
        int col = 4 * (c + 16 * h2);
        float4 v = *(const float4*)&src[d * NN + n0 + col];
        *(float4*)&dst[d][col] = v;
    }
}

// ============================================================
// 5) PATCH attention: QK + exp + l + PV; epilogue adds pos numerator.
// ============================================================
__global__ void __launch_bounds__(256, 2) attn_patch_kernel(const float* __restrict__ gating) {
    __shared__ float qs[32][132];    // [d][q]
    __shared__ float ksd[32][68];    // [d][2*k] duplicated pairs
    __shared__ float vs[32][36];     // [k][d]
    __shared__ float pT[32][132];    // [k][q]

    int tid = threadIdx.x;
    int ty = tid >> 4, tx = tid & 15;
    int qt = blockIdx.x, h = blockIdx.y, b = blockIdx.z;
    int bh = b * HH + h;
    int q0 = qt * 128;
    const float* qg = g_qT + bh * DHH * NN;
    const float* kg = g_kT + bh * DHH * NN;
    const float* vg = g_v  + bh * NN * DHH;

    load_tile_T132(qs, qg, q0, tid);

    int dx = tid & 7, ks2 = (tid >> 3) & 1;
    u64 oaccP[4][4] = {};
    float l[8] = {};

    for (int kt = 0; kt < 64; kt++) {
        int k0 = kt * 32;
        __syncthreads();
        {   // loads: ksd (duplicated), vs
            int d = tid >> 3, c = tid & 7;
            float4 kv = *(const float4*)&kg[d * NN + k0 + 4 * c];
            *(float4*)&ksd[d][8 * c]     = make_float4(kv.x, kv.x, kv.y, kv.y);
            *(float4*)&ksd[d][8 * c + 4] = make_float4(kv.z, kv.z, kv.w, kv.w);
            *(float4*)&vs[d][4 * c] = *(const float4*)&vg[(k0 + d) * DHH + 4 * c];
        }
        __syncthreads();

        // ---- QK: 8q x 2k per thread ----
        u64 sacc[4][2] = {};
        #pragma unroll
        for (int d = 0; d < 32; d++) {
            ulonglong2 a0 = *(const ulonglong2*)&qs[d][8 * ty];
            ulonglong2 a1 = *(const ulonglong2*)&qs[d][8 * ty + 4];
            u64 ap[4] = {a0.x, a0.y, a1.x, a1.y};
            u64 bd0 = *(const u64*)&ksd[d][2 * tx];
            u64 bd1 = *(const u64*)&ksd[d][2 * tx + 32];
            #pragma unroll
            for (int p = 0; p < 4; p++) {
                fma2(sacc[p][0], ap[p], bd0);
                fma2(sacc[p][1], ap[p], bd1);
            }
        }
        // ---- patch weights -> pT, accumulate l ----
        #pragma unroll
        for (int p = 0; p < 4; p++) {
            int i0 = 8 * ty + 2 * p;
            #pragma unroll
            for (int j = 0; j < 2; j++) {
                int kc = tx + 16 * j;
                float2 s = unpack2(sacc[p][j]);
                float e0 = __expf(s.x), e1 = __expf(s.y);
                pT[kc][i0] = e0; pT[kc][i0 + 1] = e1;
                l[2*p] += e0; l[2*p+1] += e1;
            }
        }
        __syncthreads();
        // ---- PV (2-way split over k within tile) ----
        #pragma unroll
        for (int kk = 0; kk < 16; kk++) {
            int k = 2 * kk + ks2;
            ulonglong2 a0 = *(const ulonglong2*)&pT[k][8 * ty];
            ulonglong2 a1 = *(const ulonglong2*)&pT[k][8 * ty + 4];
            u64 ap[4] = {a0.x, a0.y, a1.x, a1.y};
            float4 bv = *(const float4*)&vs[k][4 * dx];
            u64 bd[4] = {dup2(bv.x), dup2(bv.y), dup2(bv.z), dup2(bv.w)};
            #pragma unroll
            for (int p = 0; p < 4; p++)
                #pragma unroll
                for (int j = 0; j < 4; j++)
                    fma2(oaccP[p][j], ap[p], bd[j]);
        }
    }

    // ---- reduce l across 16 tx lanes ----
    #pragma unroll
    for (int o = 8; o; o >>= 1)
        #pragma unroll
        for (int r = 0; r < 8; r++)
            l[r] += __shfl_xor_sync(0xffffffffu, l[r], o);

    float gv = 1.f / (1.f + __expf(-gating[h]));
    float s1[8], s2[8];
    #pragma unroll
    for (int r = 0; r < 8; r++) {
        int row = q0 + 8 * ty + r;
        s1[r] = (1.f - gv) / l[r];
        s2[r] = gv * g_pinv[h * NN + row];
    }
    // ---- combine with pos numerator, split-k reduce, store ----
    #pragma unroll
    for (int p = 0; p < 4; p++) {
        float o0a[4], o1a[4];
        #pragma unroll
        for (int j = 0; j < 4; j++) {
            float2 vp = unpack2(oaccP[p][j]);
            float o0 = s1[2*p]   * vp.x;
            float o1 = s1[2*p+1] * vp.y;
            o0 += __shfl_xor_sync(0xffffffffu, o0, 8);
            o1 += __shfl_xor_sync(0xffffffffu, o1, 8);
            o0a[j] = o0; o1a[j] = o1;
        }
        if (tx < 8) {
            int row = q0 + 8 * ty + 2 * p;
            const float* pn = &g_scanF[(bh * NN + row) * DHH + 4 * tx];
            float4 p0 = *(const float4*)pn;
            float4 p1 = *(const float4*)(pn + DHH);
            float a2 = s2[2*p], b2 = s2[2*p+1];
            float4 r0 = make_float4(o0a[0] + a2*p0.x, o0a[1] + a2*p0.y,
                                    o0a[2] + a2*p0.z, o0a[3] + a2*p0.w);
            float4 r1 = make_float4(o1a[0] + b2*p1.x, o1a[1] + b2*p1.y,
                                    o1a[2] + b2*p1.z, o1a[3] + b2*p1.w);
            int col = h * 32 + 4 * tx;
            *(float4*)&g_ctx[(b * NN + row) * CC + col]     = r0;
            *(float4*)&g_ctx[(b * NN + row + 1) * CC + col] = r1;
        }
    }
}

// ============================================================
// 6) Output projection
// ============================================================
__global__ void proj_gemm_kernel(const float* __restrict__ Wp,
                                 const float* __restrict__ bp,
                                 float* __restrict__ out) {
    __shared__ float As[16][64];
    __shared__ float Bs[16][64];
    int tid = threadIdx.x;
    int ty = tid >> 4, tx = tid & 15;
    int m0 = blockIdx.x * 64, n0 = blockIdx.y * 64;
    float acc[4][4] = {};
    int arow = tid >> 2, acol = (tid & 3) * 4;
    int brow = tid >> 4, bcol = (tid & 15) * 4;

    for (int k0 = 0; k0 < 256; k0 += 16) {
        float4 av = *(const float4*)&g_ctx[(m0 + arow) * 256 + k0 + acol];
        As[acol + 0][arow] = av.x; As[acol + 1][arow] = av.y;
        As[acol + 2][arow] = av.z; As[acol + 3][arow] = av.w;
        float4 bv = *(const float4*)&Wp[(k0 + brow) * 256 + n0 + bcol];
        *(float4*)&Bs[brow][bcol] = bv;
        __syncthreads();
        #pragma unroll
        for (int kk = 0; kk < 16; kk++) {
            float4 a = *(float4*)&As[kk][4 * ty];
            float4 b = *(float4*)&Bs[kk][4 * tx];
            float aa[4] = {a.x, a.y, a.z, a.w};
            float bb[4] = {b.x, b.y, b.z, b.w};
            #pragma unroll
            for (int i = 0; i < 4; i++)
                #pragma unroll
                for (int j = 0; j < 4; j++)
                    acc[i][j] += aa[i] * bb[j];
        }
        __syncthreads();
    }
    #pragma unroll
    for (int i = 0; i < 4; i++) {
        int m = m0 + 4 * ty + i;
        #pragma unroll
        for (int j = 0; j < 4; j++) {
            int c = n0 + 4 * tx + j;
            out[m * 256 + c] = acc[i][j] + bp[c];
        }
    }
}

// ============================================================
extern "C" void kernel_launch(void* const* d_in, const int* in_sizes, int n_in,
                              void* d_out, int out_size) {
    const float* x     = (const float*)d_in[0];
    const float* Wqk   = (const float*)d_in[1];
    const float* Wv    = (const float*)d_in[2];
    const float* Wproj = (const float*)d_in[3];
    const float* bproj = (const float*)d_in[4];
    const float* Wpos  = (const float*)d_in[5];
    const float* bpos  = (const float*)d_in[6];
    const float* gate  = (const float*)d_in[7];
    float* out = (float*)d_out;

    pos_tab_kernel<<<(HH * TABW + 255) / 256, 256>>>(Wpos, bpos);
    pos_row_kernel<<<HH * NN / 8, 256>>>();
    qkv_gemm_kernel<<<dim3(BB * NN / 64, 12), 256>>>(x, Wqk, Wv);
    pos_scan_kernel<<<BB * HH, 256>>>(Wpos, bpos);
    attn_patch_kernel<<<dim3(NN / 128, HH, BB), 256>>>(gate);
    proj_gemm_kernel<<<dim3(BB * NN / 64, 4), 256>>>(Wproj, bproj, out);
}